// round 1
// baseline (speedup 1.0000x reference)
#include <cuda_runtime.h>
#include <cstdint>

// Single-output-channel 7x7 conv (cross-correlation), B=64, C=64, H=W=128, PAD=3.
// Strategy: channel-pair interleaved smem + packed fma.rn.f32x2.
//   - Block tile: 16 output rows x 128 output cols, one image b.
//   - 256 threads: lane col = tid % 128 (consecutive cols -> conflict-free 8B LDS),
//     rg = tid / 128 selects which 8-row vertical strip the thread owns.
//   - Loop over 32 channel pairs; per pair stage a 22 x 136 padded patch with the
//     two channels interleaved per pixel, so every x tap is one aligned LDS.64 and
//     every weight is one broadcast LDS.64 pair.
//   - Accumulators are f32x2 (partial sums for ch0/ch1); final output = lo + hi + bias.

#define B_DIM 64
#define C_DIM 64
#define HW 128
#define KK 7
#define PAD 3

#define TILE_H 16
#define PATCH_H 22          // TILE_H + 6
#define PITCH 136           // 128 + 6, padded to 136 pixels
#define NTHREADS 256
#define NPIX (PATCH_H * PITCH)   // 2992 pixel-pairs

typedef unsigned long long u64t;

__device__ __forceinline__ u64t fma2(u64t a, u64t b, u64t c) {
    u64t d;
    asm("fma.rn.f32x2 %0, %1, %2, %3;" : "=l"(d) : "l"(a), "l"(b), "l"(c));
    return d;
}

__device__ __forceinline__ u64t pack2(float lo, float hi) {
    u64t d;
    asm("mov.b64 %0, {%1, %2};" : "=l"(d) : "f"(lo), "f"(hi));
    return d;
}

__device__ __forceinline__ float2 unpack2(u64t v) {
    float2 f;
    asm("mov.b64 {%0, %1}, %2;" : "=f"(f.x), "=f"(f.y) : "l"(v));
    return f;
}

__global__ void __launch_bounds__(NTHREADS, 1)
conv7x7_f32x2_kernel(const float* __restrict__ x,
                     const float* __restrict__ w,
                     const float* __restrict__ bias,
                     float* __restrict__ out) {
    __shared__ u64t xs[NPIX];    // (row, colx) -> {x[c0], x[c1]} at that pixel
    __shared__ u64t ws[49];      // tap -> {w[c0], w[c1]}

    const int tid = threadIdx.x;
    const int col = tid & 127;         // output column 0..127
    const int rg  = tid >> 7;          // 0 or 1: which 8-row strip
    const int tile = blockIdx.x;       // 0..7  (16-row tiles)
    const int b    = blockIdx.y;       // 0..63
    const int oy_base = tile * TILE_H;
    const int rg8 = rg * 8;

    const float bval = bias[0];

    u64t acc[8];
#pragma unroll
    for (int r = 0; r < 8; ++r) acc[r] = 0ull;

    float* xf = reinterpret_cast<float*>(xs);

    for (int cp = 0; cp < C_DIM / 2; ++cp) {
        const int c0 = cp * 2;

        // ---- stage the 22x136 two-channel patch (zero padded) ----
        const float* xb0 = x + ((size_t)(b * C_DIM + c0) * HW) * HW;
        const float* xb1 = xb0 + (size_t)HW * HW;
        for (int idx = tid; idx < NPIX; idx += NTHREADS) {
            const int row  = idx / PITCH;
            const int colx = idx - row * PITCH;
            const int gy = oy_base + row - PAD;
            const int gx = colx - PAD;
            float v0 = 0.f, v1 = 0.f;
            if (gy >= 0 && gy < HW && gx >= 0 && gx < HW) {
                const int off = gy * HW + gx;
                v0 = xb0[off];
                v1 = xb1[off];
            }
            xf[idx * 2 + 0] = v0;
            xf[idx * 2 + 1] = v1;
        }
        // ---- stage the 49 weight pairs ----
        if (tid < 49) {
            ws[tid] = pack2(w[c0 * 49 + tid], w[(c0 + 1) * 49 + tid]);
        }
        __syncthreads();

        // ---- cache all 49 weight pairs in registers ----
        u64t wv[49];
#pragma unroll
        for (int k = 0; k < 49; ++k) wv[k] = ws[k];

        // ---- sliding-row accumulation: 14 input rows feed 8 outputs ----
#pragma unroll
        for (int ir = 0; ir < 14; ++ir) {
            const u64t* bp = &xs[(rg8 + ir) * PITCH + col];
            u64t xv[7];
#pragma unroll
            for (int dw = 0; dw < 7; ++dw) xv[dw] = bp[dw];
#pragma unroll
            for (int r = 0; r < 8; ++r) {
                const int dh = ir - r;
                if (dh >= 0 && dh < 7) {
#pragma unroll
                    for (int dw = 0; dw < 7; ++dw)
                        acc[r] = fma2(xv[dw], wv[dh * 7 + dw], acc[r]);
                }
            }
        }
        __syncthreads();
    }

    // ---- epilogue: combine channel halves, add bias, store ----
    float* ob = out + ((size_t)b * HW + oy_base + rg8) * HW + col;
#pragma unroll
    for (int r = 0; r < 8; ++r) {
        float2 f = unpack2(acc[r]);
        ob[(size_t)r * HW] = f.x + f.y + bval;
    }
}

extern "C" void kernel_launch(void* const* d_in, const int* in_sizes, int n_in,
                              void* d_out, int out_size) {
    const float* x    = (const float*)d_in[0];   // (64, 64, 128, 128)
    const float* w    = (const float*)d_in[1];   // (64, 7, 7)
    const float* bias = (const float*)d_in[2];   // (1,)
    float* out = (float*)d_out;                  // (64, 128, 128)

    dim3 grid(HW / TILE_H, B_DIM);               // 8 x 64 = 512 blocks
    conv7x7_f32x2_kernel<<<grid, NTHREADS>>>(x, w, bias, out);
}

// round 2
// speedup vs baseline: 1.7063x; 1.7063x over previous
#include <cuda_runtime.h>
#include <cstdint>

// Single-output-channel 7x7 conv, B=64, C=64, H=W=128, PAD=3. fp32.
// Round 2: channel-pair interleaved smem + packed fma.rn.f32x2, with
//   - double-buffered register-staged global loads (latency hidden under compute)
//   - 2 cols x 4 rows per thread, LDS.128 x loads (crossbar below fma demand)
//   - incremental staging addressing (no div/mod)
// Block: 16 out rows x 128 cols, 256 threads, grid (8, 64).

#define HW 128
#define C_DIM 64
#define PAD 3
#define TILE_H 16
#define PATCH_H 22           // TILE_H + 6
#define PITCH 136            // 128 + 6 + pad-to-even
#define NPIX (PATCH_H * PITCH)   // 2992 pixel-pairs
#define NTHREADS 256
#define NPAIRS 32
#define STAGE_IT 11          // 22 rows * 128 cols / 256 threads

typedef unsigned long long u64t;

__device__ __forceinline__ u64t fma2(u64t a, u64t b, u64t c) {
    u64t d;
    asm("fma.rn.f32x2 %0, %1, %2, %3;" : "=l"(d) : "l"(a), "l"(b), "l"(c));
    return d;
}
__device__ __forceinline__ u64t pack2(float lo, float hi) {
    u64t d;
    asm("mov.b64 %0, {%1, %2};" : "=l"(d) : "f"(lo), "f"(hi));
    return d;
}
__device__ __forceinline__ float2 unpack2(u64t v) {
    float2 f;
    asm("mov.b64 {%0, %1}, %2;" : "=f"(f.x), "=f"(f.y) : "l"(v));
    return f;
}

__global__ void __launch_bounds__(NTHREADS, 1)
conv7x7_db_kernel(const float* __restrict__ x,
                  const float* __restrict__ w,
                  const float* __restrict__ bias,
                  float* __restrict__ out) {
    __shared__ __align__(16) u64t xs[2][NPIX];
    __shared__ __align__(16) u64t ws[2][50];

    const int tid = threadIdx.x;
    const int cg  = tid & 63;          // column group: owns cols 2cg, 2cg+1
    const int rg  = tid >> 6;          // row group 0..3: owns rows rg*4 .. rg*4+3
    const int cbase = cg * 2;
    const int rbase = rg * 4;
    const int b  = blockIdx.y;
    const int oy = blockIdx.x * TILE_H;

    // staging invariants: idx = tid + 256*i -> colx fixed, row advances by 2
    const int colx = tid & 127;
    const int row0 = tid >> 7;                         // 0 or 1
    const int gy0  = oy + row0 - PAD;
    const int soff0 = row0 * PITCH + PAD + colx;       // smem pair index
    const int goff0 = gy0 * HW + colx;                 // gmem float index (valid only if gy in range)

    // ---- zero both buffers (halo cells persist as zero) ----
    u64t* xsf = &xs[0][0];
    for (int i = tid; i < 2 * NPIX; i += NTHREADS) xsf[i] = 0ull;
    __syncthreads();

    // ---- stage pair 0 ----
    {
        const float* xb0 = x + ((size_t)b * C_DIM) * (HW * HW);
        const float* xb1 = xb0 + HW * HW;
#pragma unroll
        for (int i = 0; i < STAGE_IT; ++i) {
            const int gy = gy0 + 2 * i;
            float v0 = 0.f, v1 = 0.f;
            if ((unsigned)gy < (unsigned)HW) {
                const int g = goff0 + 256 * i;
                v0 = xb0[g];
                v1 = xb1[g];
            }
            xs[0][soff0 + 2 * PITCH * i] = pack2(v0, v1);
        }
        if (tid < 49) ws[0][tid] = pack2(w[tid], w[49 + tid]);
    }
    __syncthreads();

    u64t acc[4][2];
#pragma unroll
    for (int r = 0; r < 4; ++r) { acc[r][0] = 0ull; acc[r][1] = 0ull; }

    float sv0[STAGE_IT], sv1[STAGE_IT];
    float wa = 0.f, wb = 0.f;

    for (int p = 0; p < NPAIRS; ++p) {
        const int bp = p & 1;

        // ---- issue next-pair global loads early (latency hidden by compute) ----
        if (p + 1 < NPAIRS) {
            const float* xb0 = x + ((size_t)(b * C_DIM + (p + 1) * 2)) * (HW * HW);
            const float* xb1 = xb0 + HW * HW;
#pragma unroll
            for (int i = 0; i < STAGE_IT; ++i) {
                const int gy = gy0 + 2 * i;
                float v0 = 0.f, v1 = 0.f;
                if ((unsigned)gy < (unsigned)HW) {
                    const int g = goff0 + 256 * i;
                    v0 = xb0[g];
                    v1 = xb1[g];
                }
                sv0[i] = v0;
                sv1[i] = v1;
            }
            if (tid < 49) {
                wa = w[(p + 1) * 2 * 49 + tid];
                wb = w[((p + 1) * 2 + 1) * 49 + tid];
            }
        }

        // ---- weights for this pair -> registers (broadcast LDS.128) ----
        u64t wv[49];
        {
            const ulonglong2* wp = reinterpret_cast<const ulonglong2*>(&ws[bp][0]);
#pragma unroll
            for (int q = 0; q < 24; ++q) {
                ulonglong2 t = wp[q];
                wv[2 * q]     = t.x;
                wv[2 * q + 1] = t.y;
            }
            wv[48] = ws[bp][48];
        }

        // ---- sliding-row compute: 10 input rows feed 4 output rows x 2 cols ----
#pragma unroll
        for (int ir = 0; ir < 10; ++ir) {
            const ulonglong2* rp = reinterpret_cast<const ulonglong2*>(
                &xs[bp][(rbase + ir) * PITCH + cbase]);
            u64t xr[8];
#pragma unroll
            for (int q = 0; q < 4; ++q) {
                ulonglong2 t = rp[q];
                xr[2 * q]     = t.x;
                xr[2 * q + 1] = t.y;
            }
#pragma unroll
            for (int r = 0; r < 4; ++r) {
                const int dh = ir - r;
                if (dh >= 0 && dh < 7) {
#pragma unroll
                    for (int dw = 0; dw < 7; ++dw) {
                        const u64t wk = wv[dh * 7 + dw];
                        acc[r][0] = fma2(xr[dw],     wk, acc[r][0]);
                        acc[r][1] = fma2(xr[dw + 1], wk, acc[r][1]);
                    }
                }
            }
        }

        // ---- commit next-pair patch into the other buffer ----
        if (p + 1 < NPAIRS) {
#pragma unroll
            for (int i = 0; i < STAGE_IT; ++i)
                xs[bp ^ 1][soff0 + 2 * PITCH * i] = pack2(sv0[i], sv1[i]);
            if (tid < 49) ws[bp ^ 1][tid] = pack2(wa, wb);
            __syncthreads();
        }
    }

    // ---- epilogue: combine channel halves, add bias, vector store ----
    const float bv = bias[0];
#pragma unroll
    for (int r = 0; r < 4; ++r) {
        float2 a0 = unpack2(acc[r][0]);
        float2 a1 = unpack2(acc[r][1]);
        float2 o;
        o.x = a0.x + a0.y + bv;
        o.y = a1.x + a1.y + bv;
        *reinterpret_cast<float2*>(
            out + ((size_t)b * HW + oy + rbase + r) * HW + cbase) = o;
    }
}

extern "C" void kernel_launch(void* const* d_in, const int* in_sizes, int n_in,
                              void* d_out, int out_size) {
    const float* x    = (const float*)d_in[0];   // (64, 64, 128, 128)
    const float* w    = (const float*)d_in[1];   // (64, 7, 7)
    const float* bias = (const float*)d_in[2];   // (1,)
    float* out = (float*)d_out;                  // (64, 128, 128)

    dim3 grid(HW / TILE_H, 64);                  // 8 x 64 = 512 blocks
    conv7x7_db_kernel<<<grid, NTHREADS>>>(x, w, bias, out);
}

// round 4
// speedup vs baseline: 2.2406x; 1.3131x over previous
#include <cuda_runtime.h>
#include <cstdint>

// Single-output-channel 7x7 conv, B=64, C=64, H=W=128, PAD=3. fp32.
// Round 3: channel-pair f32x2 + double-buffered staging (as R2), plus:
//   - sliding weight-row window (live w regs 98 -> ~56)
//   - __launch_bounds__(256, 2): 2 CTAs/SM -> occupancy 25%
// Block: 16 out rows x 128 cols, 256 threads, grid (8, 64).

#define HW 128
#define C_DIM 64
#define PAD 3
#define TILE_H 16
#define PATCH_H 22           // TILE_H + 6
#define PITCH 136            // 128 + 6 + pad-to-even
#define NPIX (PATCH_H * PITCH)   // 2992 pixel-pairs
#define NTHREADS 256
#define NPAIRS 32
#define STAGE_IT 11          // 22 rows * 128 cols / 256 threads

typedef unsigned long long u64t;

__device__ __forceinline__ u64t fma2(u64t a, u64t b, u64t c) {
    u64t d;
    asm("fma.rn.f32x2 %0, %1, %2, %3;" : "=l"(d) : "l"(a), "l"(b), "l"(c));
    return d;
}
__device__ __forceinline__ u64t pack2(float lo, float hi) {
    u64t d;
    asm("mov.b64 %0, {%1, %2};" : "=l"(d) : "f"(lo), "f"(hi));
    return d;
}
__device__ __forceinline__ float2 unpack2(u64t v) {
    float2 f;
    asm("mov.b64 {%0, %1}, %2;" : "=f"(f.x), "=f"(f.y) : "l"(v));
    return f;
}

__global__ void __launch_bounds__(NTHREADS, 2)
conv7x7_occ2_kernel(const float* __restrict__ x,
                    const float* __restrict__ w,
                    const float* __restrict__ bias,
                    float* __restrict__ out) {
    __shared__ __align__(16) u64t xs[2][NPIX];     // 46.75 KB
    __shared__ __align__(16) u64t ws[2][7][8];     // 0.875 KB (rows padded to 8 pairs)

    const int tid = threadIdx.x;
    const int cg  = tid & 63;          // owns cols 2cg, 2cg+1
    const int rg  = tid >> 6;          // owns rows rg*4 .. rg*4+3
    const int cbase = cg * 2;
    const int rbase = rg * 4;
    const int b  = blockIdx.y;
    const int oy = blockIdx.x * TILE_H;

    // staging invariants: idx = tid + 256*i -> colx fixed, row advances by 2
    const int colx = tid & 127;
    const int row0 = tid >> 7;                         // 0 or 1
    const int gy0  = oy + row0 - PAD;
    const int soff0 = row0 * PITCH + PAD + colx;       // smem pair index
    const int goff0 = gy0 * HW + colx;                 // gmem float index

    // weight staging index (tid < 49): row = tid/7, col = tid%7
    const int wrow = tid / 7;
    const int wcol = tid - wrow * 7;

    // ---- zero both x buffers (halo cells persist as zero) ----
    u64t* xsf = &xs[0][0];
    for (int i = tid; i < 2 * NPIX; i += NTHREADS) xsf[i] = 0ull;
    __syncthreads();

    // ---- stage pair 0 ----
    {
        const float* xb0 = x + ((size_t)b * C_DIM) * (HW * HW);
        const float* xb1 = xb0 + HW * HW;
#pragma unroll
        for (int i = 0; i < STAGE_IT; ++i) {
            const int gy = gy0 + 2 * i;
            float v0 = 0.f, v1 = 0.f;
            if ((unsigned)gy < (unsigned)HW) {
                const int g = goff0 + 256 * i;
                v0 = xb0[g];
                v1 = xb1[g];
            }
            xs[0][soff0 + 2 * PITCH * i] = pack2(v0, v1);
        }
        if (tid < 49) ws[0][wrow][wcol] = pack2(w[tid], w[49 + tid]);
    }
    __syncthreads();

    u64t acc[4][2];
#pragma unroll
    for (int r = 0; r < 4; ++r) { acc[r][0] = 0ull; acc[r][1] = 0ull; }

    u64t sv[STAGE_IT];
    float wa = 0.f, wb = 0.f;

    for (int p = 0; p < NPAIRS; ++p) {
        const int bp = p & 1;

        // ---- issue next-pair global loads early (hidden under compute) ----
        if (p + 1 < NPAIRS) {
            const float* xb0 = x + ((size_t)(b * C_DIM + (p + 1) * 2)) * (HW * HW);
            const float* xb1 = xb0 + HW * HW;
#pragma unroll
            for (int i = 0; i < STAGE_IT; ++i) {
                const int gy = gy0 + 2 * i;
                float v0 = 0.f, v1 = 0.f;
                if ((unsigned)gy < (unsigned)HW) {
                    const int g = goff0 + 256 * i;
                    v0 = xb0[g];
                    v1 = xb1[g];
                }
                sv[i] = pack2(v0, v1);
            }
            if (tid < 49) {
                wa = w[(p + 1) * 2 * 49 + tid];
                wb = w[((p + 1) * 2 + 1) * 49 + tid];
            }
        }

        // ---- compute: sliding rows; weight rows loaded on first use ----
        u64t wv[7][7];
#pragma unroll
        for (int ir = 0; ir < 10; ++ir) {
            if (ir < 7) {
                // load weight row `ir` (7 pairs): 3x LDS.128 + 1x LDS.64 broadcast
                const ulonglong2* wp =
                    reinterpret_cast<const ulonglong2*>(&ws[bp][ir][0]);
                ulonglong2 t0 = wp[0];
                ulonglong2 t1 = wp[1];
                ulonglong2 t2 = wp[2];
                wv[ir][0] = t0.x; wv[ir][1] = t0.y;
                wv[ir][2] = t1.x; wv[ir][3] = t1.y;
                wv[ir][4] = t2.x; wv[ir][5] = t2.y;
                wv[ir][6] = ws[bp][ir][6];
            }
            const ulonglong2* rp = reinterpret_cast<const ulonglong2*>(
                &xs[bp][(rbase + ir) * PITCH + cbase]);
            u64t xr[8];
#pragma unroll
            for (int q = 0; q < 4; ++q) {
                ulonglong2 t = rp[q];
                xr[2 * q]     = t.x;
                xr[2 * q + 1] = t.y;
            }
#pragma unroll
            for (int r = 0; r < 4; ++r) {
                const int dh = ir - r;
                if (dh >= 0 && dh < 7) {
#pragma unroll
                    for (int dw = 0; dw < 7; ++dw) {
                        const u64t wk = wv[dh][dw];
                        acc[r][0] = fma2(xr[dw],     wk, acc[r][0]);
                        acc[r][1] = fma2(xr[dw + 1], wk, acc[r][1]);
                    }
                }
            }
        }

        // ---- commit next-pair patch into the other buffer ----
        if (p + 1 < NPAIRS) {
#pragma unroll
            for (int i = 0; i < STAGE_IT; ++i)
                xs[bp ^ 1][soff0 + 2 * PITCH * i] = sv[i];
            if (tid < 49) ws[bp ^ 1][wrow][wcol] = pack2(wa, wb);
            __syncthreads();
        }
    }

    // ---- epilogue: combine channel halves, add bias, vector store ----
    const float bv = bias[0];
#pragma unroll
    for (int r = 0; r < 4; ++r) {
        float2 a0 = unpack2(acc[r][0]);
        float2 a1 = unpack2(acc[r][1]);
        float2 o;
        o.x = a0.x + a0.y + bv;
        o.y = a1.x + a1.y + bv;
        *reinterpret_cast<float2*>(
            out + ((size_t)b * HW + oy + rbase + r) * HW + cbase) = o;
    }
}

extern "C" void kernel_launch(void* const* d_in, const int* in_sizes, int n_in,
                              void* d_out, int out_size) {
    const float* x    = (const float*)d_in[0];   // (64, 64, 128, 128)
    const float* w    = (const float*)d_in[1];   // (64, 7, 7)
    const float* bias = (const float*)d_in[2];   // (1,)
    float* out = (float*)d_out;                  // (64, 128, 128)

    dim3 grid(HW / TILE_H, 64);                  // 8 x 64 = 512 blocks
    conv7x7_occ2_kernel<<<grid, NTHREADS>>>(x, w, bias, out);
}

// round 8
// speedup vs baseline: 4.5175x; 2.0162x over previous
#include <cuda_runtime.h>
#include <cstdint>

// 7x7 single-out-channel conv via legacy mma.sync tf32 implicit GEMM.
// D_o[pix, dw] accumulates over dh in a 7-deep register ring; epilogue
// shift-sums over dw through padded smem. CTA = 32 output rows of one image,
// 128 threads (4 warps x 2 m-tiles of 16 pixels). grid (4, 64).

#define HW 128
#define HW2 (HW * HW)
#define C_DIM 64
#define BAND 32
#define NT 128

static __device__ __forceinline__ uint32_t f2tf(float v) {
    uint32_t r;
    asm("cvt.rna.tf32.f32 %0, %1;" : "=r"(r) : "f"(v));
    return r;
}

static __device__ __forceinline__ void mma8(float (&d)[4], const uint32_t (&a)[4],
                                            uint32_t b0, uint32_t b1) {
    asm("mma.sync.aligned.m16n8k8.row.col.f32.tf32.tf32.f32 "
        "{%0,%1,%2,%3}, {%4,%5,%6,%7}, {%8,%9}, {%0,%1,%2,%3};"
        : "+f"(d[0]), "+f"(d[1]), "+f"(d[2]), "+f"(d[3])
        : "r"(a[0]), "r"(a[1]), "r"(a[2]), "r"(a[3]), "r"(b0), "r"(b1));
}

__global__ void __launch_bounds__(NT, 2)
conv7x7_mma(const float* __restrict__ x, const float* __restrict__ w,
            const float* __restrict__ bias, float* __restrict__ out)
{
    __shared__ unsigned long long s_bw[7][8][32];  // B fragments per (dh, kstep, lane)
    __shared__ float s_epi[2][HW * 9];             // epilogue shift buffer (pitch 9)

    const int tid  = threadIdx.x;
    const int wid  = tid >> 5;
    const int lane = tid & 31;
    const int g    = lane >> 2;       // group id (pixel within tile)
    const int q    = lane & 3;        // thread-in-group (k quad)
    const int cq2  = 2 * q;           // channel pair base for this thread
    const int pb   = wid * 32 + g;    // pixel base (tile 0)

    const int b      = blockIdx.y;
    const int ostart = blockIdx.x * BAND;
    const int oend   = ostart + BAND;
    const int rlo    = (ostart - 3 < 0) ? 0 : ostart - 3;
    const int rhi    = (oend + 2 > HW - 1) ? HW - 1 : oend + 2;

    // ---- stage B fragments: k-index kq maps to channel ks*8 + perm(kq),
    //      perm(q)=2q, perm(q+4)=2q+1 (matches A-side LDG.pairing) ----
    for (int i = tid; i < 7 * 8 * 32; i += NT) {
        const int dh = i >> 8;
        const int rem = i & 255;
        const int ks = rem >> 5;
        const int ln = rem & 31;
        const int qq = ln & 3;
        const int dw = ln >> 2;               // n-index
        const int c0 = ks * 8 + 2 * qq;
        unsigned long long lo = 0, hi = 0;
        if (dw < 7) {
            lo = f2tf(w[c0 * 49 + dh * 7 + dw]);
            hi = f2tf(w[(c0 + 1) * 49 + dh * 7 + dw]);
        }
        s_bw[dh][ks][ln] = lo | (hi << 32);
    }
    __syncthreads();

    const float bv = bias[0];
    const float* xb = x + (size_t)b * C_DIM * HW2;
    float* outb = out + (size_t)b * HW2;

    float acc[7][2][4];
#pragma unroll
    for (int j = 0; j < 7; ++j)
#pragma unroll
        for (int t = 0; t < 2; ++t)
#pragma unroll
            for (int k2 = 0; k2 < 4; ++k2) acc[j][t][k2] = 0.f;

    uint32_t ab0[2][8][4], ab1[2][8][4];
    int epar = 0;

#define LOAD_ROW(buf, rr)                                                     \
    {                                                                         \
        const float* xr_ = xb + (rr) * HW + pb + cq2 * HW2;                   \
        _Pragma("unroll") for (int t_ = 0; t_ < 2; ++t_)                      \
        _Pragma("unroll") for (int ks_ = 0; ks_ < 8; ++ks_) {                 \
            const float* p_ = xr_ + ks_ * 8 * HW2 + t_ * 16;                  \
            buf[t_][ks_][0] = __float_as_uint(p_[0]);                         \
            buf[t_][ks_][1] = __float_as_uint(p_[8]);                         \
            buf[t_][ks_][2] = __float_as_uint(p_[HW2]);                       \
            buf[t_][ks_][3] = __float_as_uint(p_[HW2 + 8]);                   \
        }                                                                     \
    }

#define CVT_BUF(buf)                                                          \
    {                                                                         \
        _Pragma("unroll") for (int t_ = 0; t_ < 2; ++t_)                      \
        _Pragma("unroll") for (int ks_ = 0; ks_ < 8; ++ks_)                   \
        _Pragma("unroll") for (int i_ = 0; i_ < 4; ++i_)                      \
            buf[t_][ks_][i_] = f2tf(__uint_as_float(buf[t_][ks_][i_]));       \
    }

#define EPILOGUE(A, o_)                                                       \
    {                                                                         \
        float* sb_ = s_epi[epar];                                             \
        epar ^= 1;                                                            \
        _Pragma("unroll") for (int t_ = 0; t_ < 2; ++t_) {                    \
            const int p_ = pb + t_ * 16;                                      \
            sb_[p_ * 9 + cq2]           = A[t_][0];                           \
            sb_[p_ * 9 + cq2 + 1]       = A[t_][1];                           \
            sb_[(p_ + 8) * 9 + cq2]     = A[t_][2];                           \
            sb_[(p_ + 8) * 9 + cq2 + 1] = A[t_][3];                           \
        }                                                                     \
        __syncthreads();                                                      \
        float s_ = bv;                                                        \
        _Pragma("unroll") for (int dw_ = 0; dw_ < 7; ++dw_) {                 \
            const int p_ = tid + dw_ - 3;                                     \
            if ((unsigned)p_ < (unsigned)HW) s_ += sb_[p_ * 9 + dw_];         \
        }                                                                     \
        outb[(o_) * HW + tid] = s_;                                           \
    }

#define BODY(cur, nxt)                                                        \
    {                                                                         \
        if (r < rhi) LOAD_ROW(nxt, r + 1);                                    \
        CVT_BUF(cur);                                                         \
        _Pragma("unroll") for (int j_ = 0; j_ < 7; ++j_) {                    \
            const int o_ = r - 3 + j_;                                        \
            if (o_ >= ostart && o_ < oend) {                                  \
                const int dh_ = 6 - j_;                                       \
                _Pragma("unroll") for (int ks_ = 0; ks_ < 8; ++ks_) {         \
                    const unsigned long long bb_ = s_bw[dh_][ks_][lane];      \
                    const uint32_t b0_ = (uint32_t)bb_;                       \
                    const uint32_t b1_ = (uint32_t)(bb_ >> 32);               \
                    mma8(acc[j_][0], cur[0][ks_], b0_, b1_);                  \
                    mma8(acc[j_][1], cur[1][ks_], b0_, b1_);                  \
                }                                                             \
            }                                                                 \
        }                                                                     \
        if (r - 3 >= ostart) EPILOGUE(acc[0], r - 3);                         \
        _Pragma("unroll") for (int j_ = 0; j_ < 6; ++j_)                      \
        _Pragma("unroll") for (int t_ = 0; t_ < 2; ++t_)                      \
        _Pragma("unroll") for (int k_ = 0; k_ < 4; ++k_)                      \
            acc[j_][t_][k_] = acc[j_ + 1][t_][k_];                            \
        _Pragma("unroll") for (int t_ = 0; t_ < 2; ++t_)                      \
        _Pragma("unroll") for (int k_ = 0; k_ < 4; ++k_)                      \
            acc[6][t_][k_] = 0.f;                                             \
    }

    LOAD_ROW(ab0, rlo);
    int r = rlo;
    while (true) {
        BODY(ab0, ab1);
        ++r;
        if (r > rhi) break;
        BODY(ab1, ab0);
        ++r;
        if (r > rhi) break;
    }

    // tail: after final shift, acc[j] holds o = rhi - 2 + j
#pragma unroll
    for (int jj = 0; jj < 6; ++jj) {
        const int o = rhi - 2 + jj;
        if (o >= ostart && o < oend) EPILOGUE(acc[jj], o);
    }
}

extern "C" void kernel_launch(void* const* d_in, const int* in_sizes, int n_in,
                              void* d_out, int out_size) {
    const float* x    = (const float*)d_in[0];   // (64, 64, 128, 128)
    const float* w    = (const float*)d_in[1];   // (64, 7, 7)
    const float* bias = (const float*)d_in[2];   // (1,)
    float* out = (float*)d_out;                  // (64, 128, 128)

    dim3 grid(HW / BAND, 64);                    // 4 x 64 = 256 CTAs
    conv7x7_mma<<<grid, NT>>>(x, w, bias, out);
}